// round 2
// baseline (speedup 1.0000x reference)
#include <cuda_runtime.h>

#define BQ 64
#define TQ 2048
#define HD 128
#define M_TOTAL (BQ * TQ)

// Scratch for x_proj (allocation-free rule: __device__ global array)
__device__ float g_xproj[(size_t)M_TOTAL * HD];

// ---------------------------------------------------------------------------
// GEMM: C[m][n] = sum_k A[m][k] * W[n][k] + bias[n] (+ bias2[n])
// M tiled 64 rows per CTA, N = K = 128 fixed. 256 threads, 4x8 register tile.
// K split in two 64-chunks so static shared stays at 48KB.
// ---------------------------------------------------------------------------
__global__ __launch_bounds__(256, 2) void gemm128_kernel(
    const float* __restrict__ A, const float* __restrict__ W,
    const float* __restrict__ bias, const float* __restrict__ bias2,
    float* __restrict__ C)
{
    __shared__ float Wt[64 * 128];  // [k][n], k-chunk major  (32KB)
    __shared__ float At[64 * 64];   // [k][m]                 (16KB)

    const int tid = threadIdx.x;
    const int m0 = blockIdx.x * 64;
    const int tx = tid & 15;   // n: cols tx*8 .. +7
    const int ty = tid >> 4;   // m: rows ty*4 .. +3

    float acc[4][8];
#pragma unroll
    for (int i = 0; i < 4; i++)
#pragma unroll
        for (int j = 0; j < 8; j++) acc[i][j] = 0.f;

#pragma unroll
    for (int kc = 0; kc < 2; kc++) {
        // stage W chunk transposed: Wt[k][n] = W[n][kc*64 + k]
        for (int i = tid; i < 128 * 16; i += 256) {  // 2048 float4
            int n  = i >> 4;
            int k0 = (i & 15) << 2;
            float4 v = *(const float4*)(W + (size_t)n * 128 + kc * 64 + k0);
            Wt[(k0 + 0) * 128 + n] = v.x;
            Wt[(k0 + 1) * 128 + n] = v.y;
            Wt[(k0 + 2) * 128 + n] = v.z;
            Wt[(k0 + 3) * 128 + n] = v.w;
        }
        // stage A chunk transposed: At[k][m] = A[m0+m][kc*64 + k]
        for (int i = tid; i < 64 * 16; i += 256) {   // 1024 float4
            int m  = i >> 4;
            int k0 = (i & 15) << 2;
            float4 v = *(const float4*)(A + (size_t)(m0 + m) * 128 + kc * 64 + k0);
            At[(k0 + 0) * 64 + m] = v.x;
            At[(k0 + 1) * 64 + m] = v.y;
            At[(k0 + 2) * 64 + m] = v.z;
            At[(k0 + 3) * 64 + m] = v.w;
        }
        __syncthreads();

#pragma unroll 4
        for (int k = 0; k < 64; k++) {
            float4 a  = *(const float4*)(At + k * 64 + ty * 4);
            float4 w0 = *(const float4*)(Wt + k * 128 + tx * 8);
            float4 w1 = *(const float4*)(Wt + k * 128 + tx * 8 + 4);
            float av[4] = {a.x, a.y, a.z, a.w};
            float wv[8] = {w0.x, w0.y, w0.z, w0.w, w1.x, w1.y, w1.z, w1.w};
#pragma unroll
            for (int i = 0; i < 4; i++)
#pragma unroll
                for (int j = 0; j < 8; j++) acc[i][j] += av[i] * wv[j];
        }
        __syncthreads();
    }

    // epilogue
    float bb[8];
#pragma unroll
    for (int j = 0; j < 8; j++) {
        bb[j] = bias[tx * 8 + j];
        if (bias2) bb[j] += bias2[tx * 8 + j];
    }
#pragma unroll
    for (int i = 0; i < 4; i++) {
        const int m = m0 + ty * 4 + i;
        float* crow = C + (size_t)m * 128 + tx * 8;
#pragma unroll
        for (int j = 0; j < 8; j++) crow[j] = acc[i][j] + bb[j];
    }
}

// ---------------------------------------------------------------------------
// Recurrence: one CTA per batch row. 256 threads = (j in [0,128), half in {0,1}).
// W_hh rows held in registers (64 floats/thread). h lives in SMEM.
// h_new[j] = tanh(xp[t][j] + sum_k h[k] * W_hh[j][k])
// ---------------------------------------------------------------------------
__global__ __launch_bounds__(256, 1) void rnn_rec_kernel(
    const float* __restrict__ xproj, const float* __restrict__ Whh,
    float* __restrict__ hidden)
{
    __shared__ float sh_h[HD];
    __shared__ float sh_part[HD];

    const int tid  = threadIdx.x;
    const int j    = tid & 127;
    const int half = tid >> 7;
    const int b    = blockIdx.x;

    // load my 64 weights W_hh[j][half*64 + k] as 16 float4 (registers)
    float4 w[16];
#pragma unroll
    for (int i = 0; i < 16; i++)
        w[i] = *(const float4*)(Whh + (size_t)j * 128 + half * 64 + i * 4);

    if (tid < HD) sh_h[tid] = 0.f;

    const float* xp   = xproj + (size_t)b * TQ * HD;
    float*       hout = hidden + (size_t)b * TQ * HD;

    float xp0 = 0.f, xp1 = 0.f;
    if (half == 0) {
        xp0 = xp[j];
        xp1 = xp[HD + j];
    }
    __syncthreads();

    const float* sh_base = sh_h + half * 64;

    for (int t = 0; t < TQ; t++) {
        // prefetch xp two steps ahead (hides DRAM latency)
        float xp2 = 0.f;
        if (half == 0 && t + 2 < TQ) xp2 = __ldg(xp + (size_t)(t + 2) * HD + j);

        float a0 = 0.f, a1 = 0.f, a2 = 0.f, a3 = 0.f;
#pragma unroll
        for (int i = 0; i < 16; i++) {
            float4 hv = *(const float4*)(sh_base + i * 4);
            a0 += hv.x * w[i].x;
            a1 += hv.y * w[i].y;
            a2 += hv.z * w[i].z;
            a3 += hv.w * w[i].w;
        }
        float acc = (a0 + a1) + (a2 + a3);

        if (half) sh_part[j] = acc;
        __syncthreads();   // sh_part ready; all reads of sh_h done

        if (half == 0) {
            float hnew = tanhf(acc + sh_part[j] + xp0);
            sh_h[j] = hnew;
            hout[(size_t)t * HD + j] = hnew;
        }
        xp0 = xp1;
        xp1 = xp2;
        __syncthreads();   // sh_h updated for next step
    }
}

// ---------------------------------------------------------------------------
extern "C" void kernel_launch(void* const* d_in, const int* in_sizes, int n_in,
                              void* d_out, int out_size)
{
    const float* seq  = (const float*)d_in[0];
    const float* Wih  = (const float*)d_in[1];
    const float* bih  = (const float*)d_in[2];
    const float* Whh  = (const float*)d_in[3];
    const float* bhh  = (const float*)d_in[4];
    const float* Wout = (const float*)d_in[5];
    const float* bout = (const float*)d_in[6];

    float* hid = (float*)d_out;                       // hidden_states (B,T,H)
    float* out = hid + (size_t)M_TOTAL * HD;          // output_states (B,T,H)

    float* xproj;
    cudaGetSymbolAddress((void**)&xproj, g_xproj);

    // Phase 1: x_proj = seq @ W_ih^T + b_ih + b_hh
    gemm128_kernel<<<M_TOTAL / 64, 256>>>(seq, Wih, bih, bhh, xproj);
    // Phase 2: sequential recurrence, one CTA per batch row
    rnn_rec_kernel<<<BQ, 256>>>(xproj, Whh, hid);
    // Phase 3: out = hidden @ W_out^T + b_out
    gemm128_kernel<<<M_TOTAL / 64, 256>>>(hid, Wout, bout, nullptr, out);
}

// round 4
// speedup vs baseline: 1.2536x; 1.2536x over previous
#include <cuda_runtime.h>

#define BQ 64
#define TQ 2048
#define HD 128
#define M_TOTAL (BQ * TQ)

// Scratch for x_proj (allocation-free rule: __device__ global array)
__device__ float g_xproj[(size_t)M_TOTAL * HD];

// ---- packed fp32x2 helpers (sm_100+: FFMA2) --------------------------------
__device__ __forceinline__ void ffma2(unsigned long long& d,
                                      unsigned long long a,
                                      unsigned long long b) {
    asm("fma.rn.f32x2 %0, %1, %2, %0;" : "+l"(d) : "l"(a), "l"(b));
}
__device__ __forceinline__ unsigned long long pack2(float lo, float hi) {
    unsigned long long p;
    asm("mov.b64 %0, {%1, %2};" : "=l"(p) : "r"(__float_as_uint(lo)), "r"(__float_as_uint(hi)));
    return p;
}
__device__ __forceinline__ void unpack2(unsigned long long p, float& lo, float& hi) {
    unsigned int a, b;
    asm("mov.b64 {%0, %1}, %2;" : "=r"(a), "=r"(b) : "l"(p));
    lo = __uint_as_float(a);
    hi = __uint_as_float(b);
}

// ---------------------------------------------------------------------------
// GEMM: C[m][n] = sum_k A[m][k] * W[n][k] + bias[n] (+ bias2[n])
// 64 rows per CTA, N=K=128. 256 threads, 4x8 register tile, FFMA2 packed.
// Staging remapped so STS are bank-conflict-free (lanes -> consecutive n/m).
// ---------------------------------------------------------------------------
__global__ __launch_bounds__(256, 2) void gemm128_kernel(
    const float* __restrict__ A, const float* __restrict__ W,
    const float* __restrict__ bias, const float* __restrict__ bias2,
    float* __restrict__ C)
{
    __shared__ __align__(16) float Wt[64 * 128];  // [k][n]  (32KB)
    __shared__ __align__(16) float At[64 * 64];   // [k][m]  (16KB)

    const int tid = threadIdx.x;
    const int m0 = blockIdx.x * 64;
    const int tx = tid & 15;   // n: cols tx*8 .. +7
    const int ty = tid >> 4;   // m: rows ty*4 .. +3

    unsigned long long acc2[4][4];
#pragma unroll
    for (int i = 0; i < 4; i++)
#pragma unroll
        for (int j = 0; j < 4; j++) acc2[i][j] = 0ull;

#pragma unroll
    for (int kc = 0; kc < 2; kc++) {
        // W staging: lanes cover 32 consecutive n -> STS bank-conflict-free.
        for (int i = tid; i < 128 * 16; i += 256) {
            int n  = i & 127;
            int k0 = (i >> 7) << 2;
            float4 v = *(const float4*)(W + (size_t)n * 128 + kc * 64 + k0);
            Wt[(k0 + 0) * 128 + n] = v.x;
            Wt[(k0 + 1) * 128 + n] = v.y;
            Wt[(k0 + 2) * 128 + n] = v.z;
            Wt[(k0 + 3) * 128 + n] = v.w;
        }
        // A staging: lanes cover 32 consecutive m -> STS bank-conflict-free.
        for (int i = tid; i < 64 * 16; i += 256) {
            int m  = i & 63;
            int k0 = (i >> 6) << 2;
            float4 v = *(const float4*)(A + (size_t)(m0 + m) * 128 + kc * 64 + k0);
            At[(k0 + 0) * 64 + m] = v.x;
            At[(k0 + 1) * 64 + m] = v.y;
            At[(k0 + 2) * 64 + m] = v.z;
            At[(k0 + 3) * 64 + m] = v.w;
        }
        __syncthreads();

#pragma unroll 4
        for (int k = 0; k < 64; k++) {
            float4 a = *(const float4*)(At + k * 64 + ty * 4);
            ulonglong2 w0 = *(const ulonglong2*)(Wt + k * 128 + tx * 8);
            ulonglong2 w1 = *(const ulonglong2*)(Wt + k * 128 + tx * 8 + 4);
            unsigned long long ad[4];
            ad[0] = pack2(a.x, a.x);
            ad[1] = pack2(a.y, a.y);
            ad[2] = pack2(a.z, a.z);
            ad[3] = pack2(a.w, a.w);
#pragma unroll
            for (int i = 0; i < 4; i++) {
                ffma2(acc2[i][0], ad[i], w0.x);
                ffma2(acc2[i][1], ad[i], w0.y);
                ffma2(acc2[i][2], ad[i], w1.x);
                ffma2(acc2[i][3], ad[i], w1.y);
            }
        }
        __syncthreads();
    }

    // epilogue
    float bb[8];
#pragma unroll
    for (int j = 0; j < 8; j++) {
        bb[j] = bias[tx * 8 + j];
        if (bias2) bb[j] += bias2[tx * 8 + j];
    }
#pragma unroll
    for (int i = 0; i < 4; i++) {
        const int m = m0 + ty * 4 + i;
        float c[8];
#pragma unroll
        for (int j = 0; j < 4; j++) unpack2(acc2[i][j], c[2 * j], c[2 * j + 1]);
#pragma unroll
        for (int j = 0; j < 8; j++) c[j] += bb[j];
        float4* crow = (float4*)(C + (size_t)m * 128 + tx * 8);
        crow[0] = make_float4(c[0], c[1], c[2], c[3]);
        crow[1] = make_float4(c[4], c[5], c[6], c[7]);
    }
}

// ---------------------------------------------------------------------------
// Recurrence: one CTA per batch row. 256 threads: j = tid>>1, half = tid&1.
// Each thread does a 64-wide partial dot with FFMA2; pair-reduce via shfl_xor.
// Double-buffered h -> ONE barrier per step. Fast tanh = 1 - 2/(e^{2x}+1).
// ---------------------------------------------------------------------------
__global__ __launch_bounds__(256, 1) void rnn_rec_kernel(
    const float* __restrict__ xproj, const float* __restrict__ Whh,
    float* __restrict__ hidden)
{
    __shared__ __align__(16) float sh_h[2][HD];

    const int tid  = threadIdx.x;
    const int j    = tid >> 1;
    const int half = tid & 1;
    const int b    = blockIdx.x;

    // my 64 weights W_hh[j][half*64 + k], packed as 32 fp32x2 pairs
    unsigned long long w2[32];
    {
        const ulonglong2* wp = (const ulonglong2*)(Whh + (size_t)j * 128 + half * 64);
#pragma unroll
        for (int i = 0; i < 16; i++) {
            ulonglong2 v = wp[i];
            w2[2 * i]     = v.x;
            w2[2 * i + 1] = v.y;
        }
    }

    if (tid < HD) sh_h[0][tid] = 0.f;

    const float* xp   = xproj + (size_t)b * TQ * HD;
    float*       hout = hidden + (size_t)b * TQ * HD;

    // both lanes of a pair load xp[t][j] (redundant, broadcast-friendly)
    float xp0 = xp[j];
    float xp1 = xp[HD + j];
    __syncthreads();

    for (int t = 0; t < TQ; t++) {
        float xp2 = 0.f;
        if (t + 2 < TQ) xp2 = __ldg(xp + (size_t)(t + 2) * HD + j);

        const ulonglong2* hp = (const ulonglong2*)(&sh_h[t & 1][half * 64]);
        unsigned long long a2[4] = {0ull, 0ull, 0ull, 0ull};
#pragma unroll
        for (int i = 0; i < 16; i++) {
            ulonglong2 hv = hp[i];
            ffma2(a2[i & 3], hv.x, w2[2 * i]);
            ffma2(a2[i & 3], hv.y, w2[2 * i + 1]);
        }
        float s = 0.f;
#pragma unroll
        for (int i = 0; i < 4; i++) {
            float lo, hi;
            unpack2(a2[i], lo, hi);
            s += lo + hi;
        }
        // pair reduction across the two halves
        s += __shfl_xor_sync(0xffffffffu, s, 1);

        const float x = s + xp0;
        // tanh(x) = 1 - 2/(exp(2x)+1)   (~1e-6 rel err)
        const float e  = __expf(2.f * x);
        const float hn = 1.f - __fdividef(2.f, e + 1.f);

        if (!half) {
            sh_h[(t + 1) & 1][j] = hn;
            hout[(size_t)t * HD + j] = hn;
        }
        xp0 = xp1;
        xp1 = xp2;
        __syncthreads();
    }
}

// ---------------------------------------------------------------------------
extern "C" void kernel_launch(void* const* d_in, const int* in_sizes, int n_in,
                              void* d_out, int out_size)
{
    const float* seq  = (const float*)d_in[0];
    const float* Wih  = (const float*)d_in[1];
    const float* bih  = (const float*)d_in[2];
    const float* Whh  = (const float*)d_in[3];
    const float* bhh  = (const float*)d_in[4];
    const float* Wout = (const float*)d_in[5];
    const float* bout = (const float*)d_in[6];

    float* hid = (float*)d_out;                  // hidden_states (B,T,H)
    float* out = hid + (size_t)M_TOTAL * HD;     // output_states (B,T,H)

    float* xproj;
    cudaGetSymbolAddress((void**)&xproj, g_xproj);

    gemm128_kernel<<<M_TOTAL / 64, 256>>>(seq, Wih, bih, bhh, xproj);
    rnn_rec_kernel<<<BQ, 256>>>(xproj, Whh, hid);
    gemm128_kernel<<<M_TOTAL / 64, 256>>>(hid, Wout, bout, nullptr, out);
}